// round 4
// baseline (speedup 1.0000x reference)
#include <cuda_runtime.h>
#include <math.h>
#include <stdint.h>

#define THREADS 256
#define ROWS_PER_BLOCK THREADS                          // 256 (1 row/thread)
#define FLOATS_PER_BLOCK (ROWS_PER_BLOCK * 7)           // 1792
#define BYTES_PER_BLOCK (FLOATS_PER_BLOCK * 4)          // 7168

__global__ __launch_bounds__(THREADS)
void emotion_kernel(const float* __restrict__ rep,
                    const float* __restrict__ emo,
                    const float* __restrict__ WQ,
                    const float* __restrict__ WK,
                    const float* __restrict__ WD,
                    const float* __restrict__ bD,
                    float* __restrict__ out,
                    int nrows)
{
    __shared__ __align__(16) float sRepF[FLOATS_PER_BLOCK];
    __shared__ __align__(16) float sEmoF[FLOATS_PER_BLOCK];
    __shared__ float sM[56];            // M = W_Q^T @ W_K, padded 7x8
    __shared__ float sCW[8];            // colsum(W_D)[0..6], [7] = sum(b_D)
    __shared__ __align__(8) unsigned long long mbar;

    const int tid = threadIdx.x;
    const long long row0blk = (long long)blockIdx.x * ROWS_PER_BLOCK;
    const bool fullblk = (row0blk + ROWS_PER_BLOCK) <= (long long)nrows;

    const uint32_t mbar_addr = (uint32_t)__cvta_generic_to_shared(&mbar);
    const uint32_t sRep_addr = (uint32_t)__cvta_generic_to_shared(sRepF);
    const uint32_t sEmo_addr = (uint32_t)__cvta_generic_to_shared(sEmoF);

    if (tid == 0) {
        asm volatile("mbarrier.init.shared::cta.b64 [%0], 1;" :: "r"(mbar_addr) : "memory");
    }
    __syncthreads();

    // ---- stage-in: one bulk TMA per input ----
    if (fullblk) {
        if (tid == 0) {
            asm volatile("mbarrier.arrive.expect_tx.shared::cta.b64 _, [%0], %1;"
                         :: "r"(mbar_addr), "r"(2 * BYTES_PER_BLOCK) : "memory");
            const float* grep = rep + row0blk * 7;
            const float* gemo = emo + row0blk * 7;
            asm volatile("cp.async.bulk.shared::cluster.global.mbarrier::complete_tx::bytes "
                         "[%0], [%1], %2, [%3];"
                         :: "r"(sRep_addr), "l"(grep), "r"(BYTES_PER_BLOCK), "r"(mbar_addr)
                         : "memory");
            asm volatile("cp.async.bulk.shared::cluster.global.mbarrier::complete_tx::bytes "
                         "[%0], [%1], %2, [%3];"
                         :: "r"(sEmo_addr), "l"(gemo), "r"(BYTES_PER_BLOCK), "r"(mbar_addr)
                         : "memory");
        }
    } else {
        const long long total = (long long)nrows * 7;
        for (int s = tid; s < FLOATS_PER_BLOCK; s += THREADS) {
            long long i = row0blk * 7 + s;
            if (i < total) { sRepF[s] = rep[i]; sEmoF[s] = emo[i]; }
        }
    }

    // ---- per-block constant precompute (overlaps TMA) ----
    if (tid < 49) {
        int j = tid / 7, k = tid % 7;
        float acc = 0.f;
        #pragma unroll
        for (int i = 0; i < 7; ++i) acc = fmaf(WQ[i * 7 + j], WK[i * 7 + k], acc);
        sM[j * 8 + k] = acc;
    } else if (tid < 56) {
        int k = tid - 49;
        float acc = 0.f;
        #pragma unroll
        for (int j = 0; j < 7; ++j) acc += WD[j * 7 + k];
        sCW[k] = acc;
    } else if (tid == 56) {
        float acc = 0.f;
        #pragma unroll
        for (int i = 0; i < 7; ++i) acc += bD[i];
        sCW[7] = acc;
    }
    __syncthreads();   // constants + fallback staging visible

    if (fullblk) {
        asm volatile(
            "{\n\t"
            ".reg .pred P;\n\t"
            "WAIT_%=:\n\t"
            "mbarrier.try_wait.parity.acquire.cta.shared::cta.b64 P, [%0], 0;\n\t"
            "@!P bra WAIT_%=;\n\t"
            "}"
            :: "r"(mbar_addr) : "memory");
    }

    // ---- compute: 1 row per thread, scalar LDS stride 7 (conflict-free: gcd(7,32)=1) ----
    const int base = tid * 7;
    float r[7], e[7];
    #pragma unroll
    for (int j = 0; j < 7; ++j) {
        r[j] = sRepF[base + j];
        e[j] = sEmoF[base + j];
    }

    const float cb = sCW[7];
    const bool valid = (row0blk + tid) < (long long)nrows;

    float o[7];
    if (valid) {
        // t = e_row @ M
        float t[7];
        #pragma unroll
        for (int k = 0; k < 7; ++k) t[k] = 0.f;
        #pragma unroll
        for (int j = 0; j < 7; ++j) {
            float ej = e[j];
            #pragma unroll
            for (int k = 0; k < 7; ++k)
                t[k] = fmaf(ej, sM[j * 8 + k], t[k]);
        }
        // raw = r * t ; softmax over 7
        float raw[7];
        #pragma unroll
        for (int k = 0; k < 7; ++k) raw[k] = r[k] * t[k];
        float mx = raw[0];
        #pragma unroll
        for (int k = 1; k < 7; ++k) mx = fmaxf(mx, raw[k]);
        float p[7], sum = 0.f;
        #pragma unroll
        for (int k = 0; k < 7; ++k) { p[k] = __expf(raw[k] - mx); sum += p[k]; }
        float inv = __fdividef(1.f, sum);
        #pragma unroll
        for (int k = 0; k < 7; ++k) {
            float s  = p[k] * inv;
            float s3 = s * s * s;
            float d  = fmaf(s3, sCW[k], cb);
            d = fminf(1.f, fmaxf(-1.f, d));
            o[k] = r[k] + d;
        }
    } else {
        #pragma unroll
        for (int k = 0; k < 7; ++k) o[k] = 0.f;
    }

    // ---- scalar STS back into sRep (exclusive per thread, conflict-free) ----
    #pragma unroll
    for (int j = 0; j < 7; ++j) sRepF[base + j] = o[j];

    // ---- stage-out ----
    if (fullblk) {
        asm volatile("fence.proxy.async.shared::cta;" ::: "memory");
        __syncthreads();
        if (tid == 0) {
            float* gdst = out + row0blk * 7;
            asm volatile("cp.async.bulk.global.shared::cta.bulk_group [%0], [%1], %2;"
                         :: "l"(gdst), "r"(sRep_addr), "r"(BYTES_PER_BLOCK) : "memory");
            asm volatile("cp.async.bulk.commit_group;" ::: "memory");
            asm volatile("cp.async.bulk.wait_group 0;" ::: "memory");
        }
    } else {
        __syncthreads();
        const long long total = (long long)nrows * 7;
        for (int s = tid; s < FLOATS_PER_BLOCK; s += THREADS) {
            long long i = row0blk * 7 + s;
            if (i < total) out[i] = sRepF[s];
        }
    }
}

extern "C" void kernel_launch(void* const* d_in, const int* in_sizes, int n_in,
                              void* d_out, int out_size)
{
    const float* rep = (const float*)d_in[0];
    const float* emo = (const float*)d_in[1];
    const float* WQ  = (const float*)d_in[2];
    const float* WK  = (const float*)d_in[3];
    const float* WD  = (const float*)d_in[4];
    const float* bD  = (const float*)d_in[5];
    float* out = (float*)d_out;

    int nrows = in_sizes[0] / 7;
    int grid  = (nrows + ROWS_PER_BLOCK - 1) / ROWS_PER_BLOCK;

    emotion_kernel<<<grid, THREADS>>>(rep, emo, WQ, WK, WD, bD, out, nrows);
}